// round 6
// baseline (speedup 1.0000x reference)
#include <cuda_runtime.h>
#include <math.h>

#define ZDIM    4736      // 4*UNITS
#define LN10K   9.210340371976184f
#define NBLK    128
#define NTHR    256

// Device globals (no allocation allowed)
__device__ __align__(16) float g_KC[64 * 2 * 64];   // [l-1][h*64+k], l = 1..64
__device__ __align__(16) float g_VC[64 * 2 * 64];
__device__ __align__(16) float g_o[128 * 64];       // o row-major: [b][k]
__device__ unsigned g_bar1 = 0, g_bar2 = 0, g_done = 0;

__device__ __forceinline__ float sigd(float x) { return 1.0f / (1.0f + __expf(-x)); }

__device__ __forceinline__ float pe_val(int l, int i) {
    float e = (float)(2 * (i / 2)) * (1.0f / 64.0f);
    float invfreq = __expf(-e * LN10K);
    float ang = (float)l * invfreq;
    return (i & 1) ? cosf(ang) : sinf(ang);
}

// Packed dual-FMA: d = a*b + d on two f32 lanes (sm_100+ PTX).
__device__ __forceinline__ void fma2(unsigned long long& d,
                                     unsigned long long a, unsigned long long b) {
    asm("fma.rn.f32x2 %0, %1, %2, %0;" : "+l"(d) : "l"(a), "l"(b));
}
__device__ __forceinline__ float pairsum(unsigned long long v) {
    return __uint_as_float((unsigned)v) + __uint_as_float((unsigned)(v >> 32));
}

// Grid-wide barrier: all 128 blocks co-resident; tight spin for low wakeup lag.
__device__ __forceinline__ void grid_bar(unsigned* ctr) {
    __syncthreads();
    if (threadIdx.x == 0) {
        __threadfence();
        atomicAdd(ctr, 1u);
        volatile unsigned* v = (volatile unsigned*)ctr;
        while (*v < (unsigned)NBLK) { }
        __threadfence();
    }
    __syncthreads();
}

// ---------------------------------------------------------------------------
// Single fused kernel. grid = 128 (block b = batch row; also produces half a
// KC/VC row: l = bid/2 + 1, K if bid even else V). block = 256.
// ---------------------------------------------------------------------------
__global__ void __launch_bounds__(NTHR) k_fused(
        const float* __restrict__ queries, const float* __restrict__ values,
        const float* __restrict__ Wi, const float* __restrict__ bi,
        const float* __restrict__ Wm, const float* __restrict__ bm,
        const float* __restrict__ Wq, const float* __restrict__ bq,
        const float* __restrict__ Wk, const float* __restrict__ bk,
        const float* __restrict__ Wv, const float* __restrict__ bv,
        const float* __restrict__ Wo, const float* __restrict__ bo,
        const float* __restrict__ Wx, const float* __restrict__ bl,
        float* __restrict__ out, float m) {
    const int bid = blockIdx.x;
    const int t = threadIdx.x;

    __shared__ __align__(16) float Wg[8][3][64];   // phase-C gate weights
    __shared__ float Bv[8][3];
    __shared__ float x[32];
    __shared__ float aug0[64];
    __shared__ float q[128], k0[128], v0[128];
    __shared__ float pq[256], pk[256], pv[256];    // matvec half-partials
    __shared__ __align__(16) float4 cs4[256];      // colsum partials
    __shared__ float augl[64];
    __shared__ float logit[130];
    __shared__ float attn[130];
    __shared__ float ctx[128];
    __shared__ float opart[256];
    __shared__ float Hs[8][132];

    const int j0 = bid * 8;
    const int grpoff[3] = {0, 2368, 3552};         // zi, zg, zo column groups

    // ---- A0: prefetch phase-C Wx tile (latency hidden behind A/B phases)
    #pragma unroll
    for (int r = 0; r < 6; r++) {
        int idx = r * NTHR + t;
        int jj = idx & 7;
        int kg = idx >> 3;
        int g  = kg % 3;
        int k  = kg / 3;
        Wg[jj][g][k] = Wx[k * ZDIM + grpoff[g] + j0 + jj];
    }
    if (t < 24) Bv[t & 7][t >> 3] = bl[grpoff[t >> 3] + j0 + (t & 7)];

    // ---- A1: input vector
    if (t < 16)       x[t] = queries[bid * 16 + t];
    else if (t < 32)  x[t] = values[(bid / 16) * 128 + 112 + (t - 16)];

    // ---- colsum(Wm) loads in flight before first sync (independent of shared)
    float4 csacc;
    {
        const float4* wm4 = (const float4*)Wm;     // 4096 float4; col4 = t&15
        float4 acc = make_float4(0.f, 0.f, 0.f, 0.f);
        #pragma unroll
        for (int r = 0; r < 16; r++) {
            float4 v = wm4[r * NTHR + t];
            acc.x += v.x; acc.y += v.y; acc.z += v.z; acc.w += v.w;
        }
        csacc = acc;
    }
    __syncthreads();   // x visible

    // ---- A2: emb_in + PE[0]
    if (t < 64) {
        float s = bi[t];
        #pragma unroll
        for (int i = 0; i < 32; i++) s += x[i] * Wi[i * 64 + t];
        aug0[t] = s + ((t & 1) ? 1.0f : 0.0f);
    }
    cs4[t] = csacc;
    __syncthreads();   // aug0 + cs4 visible

    // ---- A3: q/k0/v0 matvec, split d-range over 2 thread halves
    {
        int col = t & 127, half = t >> 7;
        float aq = 0.f, ak = 0.f, av = 0.f;
        #pragma unroll
        for (int d = half * 32; d < half * 32 + 32; d++) {
            float a = aug0[d];
            aq += a * Wq[d * 128 + col];
            ak += a * Wk[d * 128 + col];
            av += a * Wv[d * 128 + col];
        }
        pq[t] = aq; pk[t] = ak; pv[t] = av;
    }
    __syncthreads();

    // combine q/k0/v0 (t<128) and colsum -> augl (t in [128,192))
    const int lrow = (bid >> 1) + 1;               // this block's KC/VC row
    if (t < 128) {
        q[t]  = bq[t] + pq[t] + pq[t + 128];
        k0[t] = bk[t] + pk[t] + pk[t + 128];
        v0[t] = bv[t] + pv[t] + pv[t + 128];
    } else if (t < 192) {
        int d = t - 128;
        float cs = 0.f;
        const float* base = (const float*)&cs4[d >> 2] + (d & 3);
        #pragma unroll
        for (int r = 0; r < 16; r++) cs += base[r * 64];
        augl[d] = m * cs + bm[d] + pe_val(lrow, d);
    }
    __syncthreads();

    // ---- A4: produce half a KC/VC row (even bid -> K, odd -> V), 2-way split
    {
        const float* W = (bid & 1) ? Wv : Wk;
        int col = t & 127, half = t >> 7;
        float a = 0.f;
        #pragma unroll
        for (int d = half * 32; d < half * 32 + 32; d++)
            a += augl[d] * W[d * 128 + col];
        pq[t] = a;
    }
    __syncthreads();
    if (t < 128) {
        const float* bb = (bid & 1) ? bv : bk;
        float* dst      = (bid & 1) ? g_VC : g_KC;
        dst[(lrow - 1) * 128 + t] = bb[t] + pq[t] + pq[t + 128];
    }

    grid_bar(&g_bar1);   // KC/VC published

    // ---- B1: logits (2 heads x 65)
    if (t < 130) {
        int h = (t >= 65) ? 1 : 0;
        int l = t - 65 * h;
        const float* kp = (l == 0) ? &k0[h * 64] : &g_KC[(l - 1) * 128 + h * 64];
        float s = 0.0f;
        #pragma unroll
        for (int d = 0; d < 64; d++) s += q[h * 64 + d] * kp[d];
        logit[t] = s * 0.125f;
    }
    __syncthreads();

    // ---- B2: softmax (warp 0 -> head 0, warp 1 -> head 1)
    {
        int w = t >> 5, lane = t & 31;
        if (w < 2) {
            int base = w * 65;
            float a0 = logit[base + lane];
            float a1 = logit[base + 32 + lane];
            float a2 = (lane == 0) ? logit[base + 64] : -1e30f;
            float mx = fmaxf(fmaxf(a0, a1), a2);
            #pragma unroll
            for (int off = 16; off > 0; off >>= 1)
                mx = fmaxf(mx, __shfl_xor_sync(0xffffffffu, mx, off));
            float e0 = __expf(a0 - mx);
            float e1 = __expf(a1 - mx);
            float e2 = (lane == 0) ? __expf(a2 - mx) : 0.0f;
            float sum = e0 + e1 + e2;
            #pragma unroll
            for (int off = 16; off > 0; off >>= 1)
                sum += __shfl_xor_sync(0xffffffffu, sum, off);
            float inv = 1.0f / sum;
            attn[base + lane] = e0 * inv;
            attn[base + 32 + lane] = e1 * inv;
            if (lane == 0) attn[base + 64] = e2 * inv;
        }
    }
    __syncthreads();

    // ---- B3: ctx
    if (t < 128) {
        int h = t >> 6;
        float s = attn[h * 65] * v0[t];
        #pragma unroll
        for (int l = 1; l < 65; l++) s += attn[h * 65 + l] * g_VC[(l - 1) * 128 + t];
        ctx[t] = s;
    }
    __syncthreads();

    // ---- B4: o matvec, 4-way split over hk
    {
        int col = t & 63, qtr = t >> 6;
        float s = qtr ? 0.0f : bo[col];
        const float* Wp = Wo + (qtr * 32) * 64 + col;
        #pragma unroll
        for (int hk = 0; hk < 32; hk++)
            s += ctx[qtr * 32 + hk] * Wp[hk * 64];
        opart[t] = s;
    }
    __syncthreads();
    if (t < 64)
        g_o[bid * 64 + t] = opart[t] + opart[t + 64] + opart[t + 128] + opart[t + 192];

    grid_bar(&g_bar2);   // o published

    // ---- C: gate GEMM with packed f32x2 FMA. thread = (b, jhalf)
    {
        int b = t & 127, jsel = t >> 7;
        unsigned long long o2[32];
        const unsigned long long* gp = (const unsigned long long*)(g_o + b * 64);
        #pragma unroll
        for (int i = 0; i < 32; i++) o2[i] = gp[i];

        #pragma unroll
        for (int jr = 0; jr < 4; jr++) {
            int jj = jsel * 4 + jr;
            unsigned long long zi2 = 0ull, zg2 = 0ull, zo2 = 0ull;
            const unsigned long long* wi2 = (const unsigned long long*)Wg[jj][0];
            const unsigned long long* wg2 = (const unsigned long long*)Wg[jj][1];
            const unsigned long long* wo2 = (const unsigned long long*)Wg[jj][2];
            #pragma unroll
            for (int k2 = 0; k2 < 32; k2++) {
                unsigned long long ov = o2[k2];
                fma2(zi2, ov, wi2[k2]);
                fma2(zg2, ov, wg2[k2]);
                fma2(zo2, ov, wo2[k2]);
            }
            float zi = pairsum(zi2) + Bv[jj][0];
            float zg = pairsum(zg2) + Bv[jj][1];
            float zo = pairsum(zo2) + Bv[jj][2];
            float c = sigd(zi) * tanhf(zg);
            Hs[jj][b] = sigd(zo) * tanhf(c);
        }
    }
    __syncthreads();

    // staged coalesced writes
    #pragma unroll
    for (int r = 0; r < 4; r++) {
        int idx = r * NTHR + t;
        int jj = idx & 7, bb = idx >> 3;
        out[bb * 1024 + j0 + jj] = Hs[jj][bb];
    }

    // ---- Cleanup: last block out resets barrier counters for the next replay
    __syncthreads();
    if (t == 0) {
        __threadfence();
        unsigned d = atomicAdd(&g_done, 1u);
        if (d == (unsigned)(NBLK - 1)) {
            g_bar1 = 0; g_bar2 = 0;
            __threadfence();
            g_done = 0;
        }
    }
}

// ---------------------------------------------------------------------------
// Host-side replica of the pot decay (input-independent).
static float sig_h(float x) { return 1.0f / (1.0f + expf(-x)); }
static float decay_h(float pc, float po) {
    float t0 = 0.07915332f * sig_h(100.0f * (0.0f - 0.5f)) * (1.5931877f - pc);
    float t1 = 1.0334609f  * sig_h(100.0f * (pc - 0.07879465f)) * (1.4378392f - pc);
    float t2 = 1.3365093f  * sig_h(100.0f * (po - 0.06618887f)) * (0.0f - pc);
    float t3 = 0.4505964f  * (0.0f - pc);
    return t0 + t1 + t2 + t3;
}
static float pot_scalar_h() {
    float p0 = 0.0f, p1 = 1.0f;
    const float PART = (float)(1.5573331 / 2.0);
    for (int s = 0; s < 7; s++)
        for (int d = 0; d < 2; d++) {
            float n0 = decay_h(p0, p1);
            float n1 = decay_h(p1, p0);
            p0 += n0 * PART;
            p1 += n1 * PART;
        }
    return p0;
}

extern "C" void kernel_launch(void* const* d_in, const int* in_sizes, int n_in,
                              void* d_out, int out_size) {
    const float* queries = (const float*)d_in[0];
    const float* values  = (const float*)d_in[1];
    const float* Wi      = (const float*)d_in[2];
    const float* bi      = (const float*)d_in[3];
    const float* Wm      = (const float*)d_in[4];
    const float* bm      = (const float*)d_in[5];
    const float* Wq      = (const float*)d_in[6];
    const float* bq      = (const float*)d_in[7];
    const float* Wk      = (const float*)d_in[8];
    const float* bk      = (const float*)d_in[9];
    const float* Wv      = (const float*)d_in[10];
    const float* bv      = (const float*)d_in[11];
    const float* Wo      = (const float*)d_in[12];
    const float* bo      = (const float*)d_in[13];
    const float* Wx      = (const float*)d_in[14];
    const float* bl      = (const float*)d_in[15];
    float* out = (float*)d_out;

    float m = pot_scalar_h();

    k_fused<<<NBLK, NTHR>>>(queries, values, Wi, bi, Wm, bm, Wq, bq, Wk, bk,
                            Wv, bv, Wo, bo, Wx, bl, out, m);
}